// round 3
// baseline (speedup 1.0000x reference)
#include <cuda_runtime.h>
#include <cuda_bf16.h>
#include <math.h>

// Problem constants
#define B_   8
#define T_   4096
#define NH_  16
#define MD_  64
#define FF_  256
#define HEADS_ 4
#define DH_  16
#define PEH_ 32
#define BT_  (B_ * T_)        // 32768

// ---------------- device scratch (static, no allocations) ----------------
__device__ float g_xn[(size_t)BT_ * MD_];            // LN1 output       8 MB
__device__ int   g_idx[T_ * NH_];
__device__ float g_c1[T_ * NH_];
__device__ float g_c2[T_ * NH_];
__device__ float g_bias[(size_t)T_ * HEADS_ * NH_ * NH_];   // 16 MB
__device__ float g_xu[(size_t)BT_ * (NH_ * MD_)];    // LN3 output     134 MB

// =========================================================================
// Kernel 1: LayerNorm over x rows (B*T rows of 64)
// =========================================================================
__global__ void k_ln1(const float* __restrict__ x,
                      const float* __restrict__ g1,
                      const float* __restrict__ be1)
{
    int row  = blockIdx.x * 8 + (threadIdx.x >> 5);
    int lane = threadIdx.x & 31;
    const float* xr = x + (size_t)row * 64;
    float a = xr[lane], b = xr[lane + 32];
    float s = a + b, s2 = a * a + b * b;
    #pragma unroll
    for (int o = 16; o; o >>= 1) {
        s  += __shfl_xor_sync(0xffffffffu, s, o);
        s2 += __shfl_xor_sync(0xffffffffu, s2, o);
    }
    float m = s * (1.0f / 64.0f);
    float v = s2 * (1.0f / 64.0f) - m * m;
    float r = rsqrtf(v + 1e-5f);
    size_t base = (size_t)row * 64;
    g_xn[base + lane]      = (a - m) * r * g1[lane]      + be1[lane];
    g_xn[base + lane + 32] = (b - m) * r * g1[lane + 32] + be1[lane + 32];
}

// =========================================================================
// Kernel 2: top-16 nearest neighbors per t (matches jax.lax.top_k order)
// one warp per t; keys = (dist_bits<<32)|s  -> ties broken by lower index
// =========================================================================
__global__ void k_topk(const float* __restrict__ c1,
                       const float* __restrict__ c2)
{
    __shared__ unsigned long long res[4][16];
    int warp = threadIdx.x >> 5, lane = threadIdx.x & 31;
    int t = blockIdx.x * 4 + warp;
    float c1t = c1[t], c2t = c2[t];

    unsigned long long best[16];
    #pragma unroll
    for (int i = 0; i < 16; i++) best[i] = 0xFFFFFFFFFFFFFFFFull;

    for (int s = lane; s < T_; s += 32) {
        float d1 = __fadd_rn(c1[s], -c1t);
        float d2 = __fadd_rn(c2[s], -c2t);
        float dist = __fadd_rn(__fmul_rn(d1, d1), __fmul_rn(d2, d2));
        unsigned long long key =
            ((unsigned long long)__float_as_uint(dist) << 32) | (unsigned)s;
        if (key < best[15]) {
            int p = 15;
            while (p > 0 && key < best[p - 1]) { best[p] = best[p - 1]; p--; }
            best[p] = key;
        }
    }
    // merge 32x16 sorted lists: 16 rounds of warp-min extraction
    int p = 0;
    for (int r = 0; r < 16; r++) {
        unsigned long long cand = (p < 16) ? best[p] : 0xFFFFFFFFFFFFFFFFull;
        unsigned long long m = cand;
        #pragma unroll
        for (int o = 16; o; o >>= 1) {
            unsigned long long other = __shfl_xor_sync(0xffffffffu, m, o);
            if (other < m) m = other;
        }
        if (cand == m) p++;            // unique keys -> exactly one owner
        if (lane == 0) res[warp][r] = m;
    }
    __syncwarp();
    if (lane < 16) {
        unsigned long long key = res[warp][lane];
        int s = (int)(key & 0xFFFFFFFFu);
        g_idx[t * 16 + lane] = s;
        g_c1[t * 16 + lane] = __fadd_rn(c1[s], -c1t);
        g_c2[t * 16 + lane] = __fadd_rn(c2[s], -c2t);
    }
}

// =========================================================================
// Kernel 3: relative-position bias MLP  -> g_bias[t][h][i][j]
// =========================================================================
__global__ void k_bias(const float* __restrict__ Wp1, const float* __restrict__ bp1,
                       const float* __restrict__ Wp2, const float* __restrict__ bp2)
{
    __shared__ float sW1[64], sB1[32], sW2[128], sB2[4], sc1[16], sc2[16];
    int t = blockIdx.x, tid = threadIdx.x;
    if (tid < 64)  sW1[tid] = Wp1[tid];
    if (tid < 32)  sB1[tid] = bp1[tid];
    if (tid < 128) sW2[tid] = Wp2[tid];
    if (tid < 4)   sB2[tid] = bp2[tid];
    if (tid < 16) { sc1[tid] = g_c1[t * 16 + tid]; sc2[tid] = g_c2[t * 16 + tid]; }
    __syncthreads();

    int i = tid >> 4, j = tid & 15;
    float p0 = sc1[i] - sc1[j];
    float p1 = sc2[i] - sc2[j];
    float o0 = sB2[0], o1 = sB2[1], o2 = sB2[2], o3 = sB2[3];
    #pragma unroll
    for (int k = 0; k < 32; k++) {
        float h = fmaf(p0, sW1[k], fmaf(p1, sW1[32 + k], sB1[k]));
        h = (h >= 0.0f) ? h : 0.2f * h;
        o0 = fmaf(h, sW2[k * 4 + 0], o0);
        o1 = fmaf(h, sW2[k * 4 + 1], o1);
        o2 = fmaf(h, sW2[k * 4 + 2], o2);
        o3 = fmaf(h, sW2[k * 4 + 3], o3);
    }
    int base = ((t * 4) * 16 + i) * 16 + j;  // [t][h][i][j], h-stride = 256
    g_bias[base]       = o0;
    g_bias[base + 256] = o1;
    g_bias[base + 512] = o2;
    g_bias[base + 768] = o3;
}

// =========================================================================
// Kernel 4: fused per-(b,t) block: gather -> QKV -> attn -> Wo+res -> LN2
//           -> FF (scalar branch) -> LN3 -> write xu row (1024)
// Persistent blocks; weights in SMEM (once/block); Wn1 column in registers.
// =========================================================================
#define OFF_WQ   0
#define OFF_WK   4096
#define OFF_WV   8192
#define OFF_WO   12288
#define OFF_BQ   16384
#define OFF_BK   16448
#define OFF_BV   16512
#define OFF_BO   16576
#define OFF_BN1  16640
#define OFF_WN2  16896
#define OFF_G2   17152
#define OFF_BE2  17216
#define OFF_G3   17280
#define OFF_BE3  18304
#define OFF_SC   19328
#define OFF_BN2  19332
#define OFF_X    19336
#define OFF_Q    20424
#define OFF_K    21512
#define OFF_V    22600
#define OFF_AV   23688
#define OFF_Z    24776
#define OFF_QIN  25864
#define OFF_KIN  25928
#define OFF_RED  25992
#define OFF_R    26120
#define OFF_RS   26136
#define OFF_IDX  26156
#define SMEM_ATTN_FLOATS 26176
#define SMEM_ATTN_BYTES  (SMEM_ATTN_FLOATS * 4)
#define XS 68   // padded row stride for 16x64 tiles

__global__ void __launch_bounds__(256, 1) k_attn(
    const float* __restrict__ Wq, const float* __restrict__ bq,
    const float* __restrict__ Wk, const float* __restrict__ bk,
    const float* __restrict__ Wv, const float* __restrict__ bv,
    const float* __restrict__ logit_scale,
    const float* __restrict__ Wo, const float* __restrict__ bo,
    const float* __restrict__ g2, const float* __restrict__ be2,
    const float* __restrict__ Wn1, const float* __restrict__ bn1,
    const float* __restrict__ Wn2, const float* __restrict__ bn2,
    const float* __restrict__ g3, const float* __restrict__ be3)
{
    extern __shared__ float sm[];
    int tid  = threadIdx.x;
    int wid  = tid >> 5;
    int lane = tid & 31;

    // ---- one-time weight staging ----
    for (int i = tid; i < 4096; i += 256) {
        sm[OFF_WQ + i] = Wq[i];
        sm[OFF_WK + i] = Wk[i];
        sm[OFF_WV + i] = Wv[i];
        sm[OFF_WO + i] = Wo[i];
    }
    if (tid < 64) {
        sm[OFF_BQ + tid] = bq[tid];  sm[OFF_BK + tid] = bk[tid];
        sm[OFF_BV + tid] = bv[tid];  sm[OFF_BO + tid] = bo[tid];
        sm[OFF_G2 + tid] = g2[tid];  sm[OFF_BE2 + tid] = be2[tid];
    }
    sm[OFF_BN1 + tid] = bn1[tid];
    sm[OFF_WN2 + tid] = Wn2[tid];
    for (int i = tid; i < 1024; i += 256) {
        sm[OFF_G3 + i]  = g3[i];
        sm[OFF_BE3 + i] = be3[i];
    }
    if (tid < 4)  sm[OFF_SC + tid] = expf(fminf(logit_scale[tid], logf(100.0f)));
    if (tid == 0) sm[OFF_BN2] = bn2[0];

    // Wn1 column (thread tid <-> FF unit tid) held in registers
    float wreg[64];
    #pragma unroll
    for (int d = 0; d < 64; d++) wreg[d] = Wn1[d * 256 + tid];
    __syncthreads();

    int n16 = tid >> 4;          // row 0..15
    int dq  = tid & 15;          // float4 column group
    int* sIdxS = (int*)(sm + OFF_IDX);

    const float4* wq4 = (const float4*)(sm + OFF_WQ);
    const float4* wk4 = (const float4*)(sm + OFF_WK);
    const float4* wv4 = (const float4*)(sm + OFF_WV);
    const float4* wo4 = (const float4*)(sm + OFF_WO);

    for (int tile = blockIdx.x; tile < BT_; tile += gridDim.x) {
        int t = tile & (T_ - 1);
        int b = tile >> 12;

        if (tid < 16) sIdxS[tid] = g_idx[t * 16 + tid];
        __syncthreads();

        // gather xg
        for (int i = tid; i < 1024; i += 256) {
            int n = i >> 6, e = i & 63;
            sm[OFF_X + n * XS + e] =
                g_xn[(size_t)(b * T_ + sIdxS[n]) * 64 + e];
        }
        __syncthreads();

        // ---- QKV ----
        {
            float4 aq = ((const float4*)(sm + OFF_BQ))[dq];
            float4 ak = ((const float4*)(sm + OFF_BK))[dq];
            float4 av = ((const float4*)(sm + OFF_BV))[dq];
            const float4* xr4 = (const float4*)(sm + OFF_X + n16 * XS);
            #pragma unroll
            for (int e4 = 0; e4 < 16; e4++) {
                float4 x4 = xr4[e4];
                #pragma unroll
                for (int u = 0; u < 4; u++) {
                    float x = (u == 0) ? x4.x : (u == 1) ? x4.y : (u == 2) ? x4.z : x4.w;
                    int e = e4 * 4 + u;
                    float4 w;
                    w = wq4[e * 16 + dq];
                    aq.x = fmaf(x, w.x, aq.x); aq.y = fmaf(x, w.y, aq.y);
                    aq.z = fmaf(x, w.z, aq.z); aq.w = fmaf(x, w.w, aq.w);
                    w = wk4[e * 16 + dq];
                    ak.x = fmaf(x, w.x, ak.x); ak.y = fmaf(x, w.y, ak.y);
                    ak.z = fmaf(x, w.z, ak.z); ak.w = fmaf(x, w.w, ak.w);
                    w = wv4[e * 16 + dq];
                    av.x = fmaf(x, w.x, av.x); av.y = fmaf(x, w.y, av.y);
                    av.z = fmaf(x, w.z, av.z); av.w = fmaf(x, w.w, av.w);
                }
            }
            ((float4*)(sm + OFF_Q + n16 * XS))[dq] = aq;
            ((float4*)(sm + OFF_K + n16 * XS))[dq] = ak;
            ((float4*)(sm + OFF_V + n16 * XS))[dq] = av;
        }
        __syncthreads();

        // ---- q/k inverse norms ----
        if (tid < 64) {
            int n = tid & 15, h = tid >> 4;
            const float* q = sm + OFF_Q + n * XS + h * 16;
            const float* k = sm + OFF_K + n * XS + h * 16;
            float sq = 0.0f, sk = 0.0f;
            #pragma unroll
            for (int d = 0; d < 16; d++) { sq = fmaf(q[d], q[d], sq); sk = fmaf(k[d], k[d], sk); }
            sm[OFF_QIN + h * 16 + n] = 1.0f / fmaxf(sqrtf(sq), 1e-6f);
            sm[OFF_KIN + h * 16 + n] = 1.0f / fmaxf(sqrtf(sk), 1e-6f);
        }
        __syncthreads();

        // ---- attention (64 threads: one (h,i) row each) ----
        if (tid < 64) {
            int h = tid >> 4, i = tid & 15, hb = h * 16;
            float qr[16];
            const float* qp = sm + OFF_Q + i * XS + hb;
            #pragma unroll
            for (int d = 0; d < 16; d++) qr[d] = qp[d];
            float qs = sm[OFF_QIN + hb + i] * sm[OFF_SC + h];
            const float* bias_p = g_bias + (((size_t)t * 4 + h) * 16 + i) * 16;

            float sv[16], mx = -1e30f;
            #pragma unroll
            for (int j = 0; j < 16; j++) {
                const float* kp = sm + OFF_K + j * XS + hb;
                float s = 0.0f;
                #pragma unroll
                for (int d = 0; d < 16; d++) s = fmaf(qr[d], kp[d], s);
                s = s * qs * sm[OFF_KIN + hb + j] + bias_p[j];
                sv[j] = s;
                mx = fmaxf(mx, s);
            }
            float den = 0.0f;
            #pragma unroll
            for (int j = 0; j < 16; j++) { sv[j] = expf(sv[j] - mx); den += sv[j]; }
            float inv = 1.0f / den;
            #pragma unroll
            for (int d = 0; d < 16; d++) {
                float acc = 0.0f;
                #pragma unroll
                for (int j = 0; j < 16; j++)
                    acc = fmaf(sv[j], sm[OFF_V + j * XS + hb + d], acc);
                sm[OFF_AV + i * XS + hb + d] = acc * inv;
            }
        }
        __syncthreads();

        // ---- Wo projection + residual -> Y (reuse Q buffer) ----
        {
            float4 acc = ((const float4*)(sm + OFF_BO))[dq];
            const float* ar = sm + OFF_AV + n16 * XS;
            #pragma unroll
            for (int e = 0; e < 64; e++) {
                float a = ar[e];
                float4 w = wo4[e * 16 + dq];
                acc.x = fmaf(a, w.x, acc.x); acc.y = fmaf(a, w.y, acc.y);
                acc.z = fmaf(a, w.z, acc.z); acc.w = fmaf(a, w.w, acc.w);
            }
            float4 xv = ((const float4*)(sm + OFF_X + n16 * XS))[dq];
            acc.x += xv.x; acc.y += xv.y; acc.z += xv.z; acc.w += xv.w;
            ((float4*)(sm + OFF_Q + n16 * XS))[dq] = acc;   // Y
        }
        __syncthreads();

        // ---- LN2 (warp w handles rows 2w, 2w+1) ----
        {
            #pragma unroll
            for (int rr = 0; rr < 2; rr++) {
                int r = wid * 2 + rr;
                const float* yr = sm + OFF_Q + r * XS;
                float a = yr[lane], bb = yr[lane + 32];
                float s = a + bb, s2 = a * a + bb * bb;
                #pragma unroll
                for (int o = 16; o; o >>= 1) {
                    s  += __shfl_xor_sync(0xffffffffu, s, o);
                    s2 += __shfl_xor_sync(0xffffffffu, s2, o);
                }
                float m = s * (1.0f / 64.0f);
                float v = s2 * (1.0f / 64.0f) - m * m;
                float rs = rsqrtf(v + 1e-5f);
                sm[OFF_Z + r * XS + lane] =
                    (a - m) * rs * sm[OFF_G2 + lane] + sm[OFF_BE2 + lane];
                sm[OFF_Z + r * XS + lane + 32] =
                    (bb - m) * rs * sm[OFF_G2 + lane + 32] + sm[OFF_BE2 + lane + 32];
            }
        }
        __syncthreads();

        // ---- FF: thread tid owns FF unit tid; reduce f*Wn2 per row ----
        {
            for (int n = 0; n < 16; n++) {
                const float4* z4 = (const float4*)(sm + OFF_Z + n * XS);
                float acc = sm[OFF_BN1 + tid];
                #pragma unroll
                for (int d4 = 0; d4 < 16; d4++) {
                    float4 z = z4[d4];
                    acc = fmaf(z.x, wreg[d4 * 4 + 0], acc);
                    acc = fmaf(z.y, wreg[d4 * 4 + 1], acc);
                    acc = fmaf(z.z, wreg[d4 * 4 + 2], acc);
                    acc = fmaf(z.w, wreg[d4 * 4 + 3], acc);
                }
                acc = (acc >= 0.0f) ? acc : 0.2f * acc;
                float contrib = acc * sm[OFF_WN2 + tid];
                #pragma unroll
                for (int o = 16; o; o >>= 1)
                    contrib += __shfl_xor_sync(0xffffffffu, contrib, o);
                if (lane == 0) sm[OFF_RED + n * 8 + wid] = contrib;
            }
            __syncthreads();
            if (tid < 16) {
                float s = sm[OFF_BN2];
                #pragma unroll
                for (int w2 = 0; w2 < 8; w2++) s += sm[OFF_RED + tid * 8 + w2];
                sm[OFF_R + tid] = (s >= 0.0f) ? s : 0.2f * s;
            }
        }
        __syncthreads();

        // ---- residual add + LN3 over full 1024 + write xu ----
        {
            float lsum = 0.0f, lss = 0.0f;
            for (int i = tid; i < 1024; i += 256) {
                int n = i >> 6, d = i & 63;
                float v = sm[OFF_Z + n * XS + d] + sm[OFF_R + n];
                sm[OFF_X + n * XS + d] = v;      // reuse X as xf2
                lsum += v; lss = fmaf(v, v, lss);
            }
            #pragma unroll
            for (int o = 16; o; o >>= 1) {
                lsum += __shfl_xor_sync(0xffffffffu, lsum, o);
                lss  += __shfl_xor_sync(0xffffffffu, lss, o);
            }
            if (lane == 0) { sm[OFF_RS + wid] = lsum; sm[OFF_RS + 8 + wid] = lss; }
            __syncthreads();
            if (tid == 0) {
                float S = 0.0f, S2 = 0.0f;
                #pragma unroll
                for (int w2 = 0; w2 < 8; w2++) { S += sm[OFF_RS + w2]; S2 += sm[OFF_RS + 8 + w2]; }
                float m = S * (1.0f / 1024.0f);
                float v = S2 * (1.0f / 1024.0f) - m * m;
                sm[OFF_RS + 16] = m;
                sm[OFF_RS + 17] = rsqrtf(v + 1e-5f);
            }
            __syncthreads();
            float m = sm[OFF_RS + 16], rs = sm[OFF_RS + 17];
            for (int i = tid; i < 1024; i += 256) {
                int n = i >> 6, d = i & 63;
                g_xu[(size_t)tile * 1024 + i] =
                    (sm[OFF_X + n * XS + d] - m) * rs * sm[OFF_G3 + i] + sm[OFF_BE3 + i];
            }
        }
        __syncthreads();
    }
}

// =========================================================================
// Kernel 5: fused head: out = lrelu(lrelu(xu@Wu1+bu1)@Wu2+bu2)
// 64-row block tile, full N loop inside block (no atomics)
// =========================================================================
__global__ void __launch_bounds__(256) k_head(
    const float* __restrict__ Wu1, const float* __restrict__ bu1,
    const float* __restrict__ Wu2, const float* __restrict__ bu2,
    float* __restrict__ out)
{
    __shared__ float sA[64][33];
    __shared__ float sB[32][68];
    __shared__ float sRed[64][17];

    int tid = threadIdx.x;
    int tx = tid & 15, ty = tid >> 4;
    int r0 = blockIdx.x * 64;

    float t_out[4] = {0.0f, 0.0f, 0.0f, 0.0f};

    for (int jt = 0; jt < 16; jt++) {
        int j0 = jt * 64;
        float acc[4][4];
        #pragma unroll
        for (int i = 0; i < 4; i++)
            #pragma unroll
            for (int c = 0; c < 4; c++) acc[i][c] = 0.0f;

        for (int k0 = 0; k0 < 1024; k0 += 32) {
            for (int i = tid; i < 2048; i += 256) {
                int r = i >> 5, k = i & 31;
                sA[r][k] = g_xu[(size_t)(r0 + r) * 1024 + k0 + k];
            }
            for (int i = tid; i < 2048; i += 256) {
                int k = i >> 6, j = i & 63;
                sB[k][j] = Wu1[(size_t)(k0 + k) * 1024 + j0 + j];
            }
            __syncthreads();
            #pragma unroll
            for (int k = 0; k < 32; k++) {
                float4 b4 = *(const float4*)&sB[k][tx * 4];
                float a0 = sA[ty * 4 + 0][k];
                float a1 = sA[ty * 4 + 1][k];
                float a2 = sA[ty * 4 + 2][k];
                float a3 = sA[ty * 4 + 3][k];
                acc[0][0] = fmaf(a0, b4.x, acc[0][0]); acc[0][1] = fmaf(a0, b4.y, acc[0][1]);
                acc[0][2] = fmaf(a0, b4.z, acc[0][2]); acc[0][3] = fmaf(a0, b4.w, acc[0][3]);
                acc[1][0] = fmaf(a1, b4.x, acc[1][0]); acc[1][1] = fmaf(a1, b4.y, acc[1][1]);
                acc[1][2] = fmaf(a1, b4.z, acc[1][2]); acc[1][3] = fmaf(a1, b4.w, acc[1][3]);
                acc[2][0] = fmaf(a2, b4.x, acc[2][0]); acc[2][1] = fmaf(a2, b4.y, acc[2][1]);
                acc[2][2] = fmaf(a2, b4.z, acc[2][2]); acc[2][3] = fmaf(a2, b4.w, acc[2][3]);
                acc[3][0] = fmaf(a3, b4.x, acc[3][0]); acc[3][1] = fmaf(a3, b4.y, acc[3][1]);
                acc[3][2] = fmaf(a3, b4.z, acc[3][2]); acc[3][3] = fmaf(a3, b4.w, acc[3][3]);
            }
            __syncthreads();
        }
        // fused lrelu + Wu2 partial reduction for this j-tile
        #pragma unroll
        for (int c = 0; c < 4; c++) {
            int j = j0 + tx * 4 + c;
            float bj = __ldg(&bu1[j]);
            float wj = __ldg(&Wu2[j]);
            #pragma unroll
            for (int i = 0; i < 4; i++) {
                float h = acc[i][c] + bj;
                h = (h >= 0.0f) ? h : 0.2f * h;
                t_out[i] = fmaf(wj, h, t_out[i]);
            }
        }
    }
    #pragma unroll
    for (int i = 0; i < 4; i++) sRed[ty * 4 + i][tx] = t_out[i];
    __syncthreads();
    if (tid < 64) {
        float s = 0.0f;
        #pragma unroll
        for (int x = 0; x < 16; x++) s += sRed[tid][x];
        s += __ldg(&bu2[0]);
        out[r0 + tid] = (s >= 0.0f) ? s : 0.2f * s;
    }
}

// =========================================================================
// launch
// =========================================================================
extern "C" void kernel_launch(void* const* d_in, const int* in_sizes, int n_in,
                              void* d_out, int out_size)
{
    const float* x       = (const float*)d_in[0];
    const float* coords1 = (const float*)d_in[1];
    const float* coords2 = (const float*)d_in[2];
    const float* g1      = (const float*)d_in[3];
    const float* be1     = (const float*)d_in[4];
    const float* Wq      = (const float*)d_in[5];
    const float* bq      = (const float*)d_in[6];
    const float* Wk      = (const float*)d_in[7];
    const float* bk      = (const float*)d_in[8];
    const float* Wv      = (const float*)d_in[9];
    const float* bv      = (const float*)d_in[10];
    const float* ls      = (const float*)d_in[11];
    const float* Wo      = (const float*)d_in[12];
    const float* bo      = (const float*)d_in[13];
    const float* Wp1     = (const float*)d_in[14];
    const float* bp1     = (const float*)d_in[15];
    const float* Wp2     = (const float*)d_in[16];
    const float* bp2     = (const float*)d_in[17];
    const float* g2      = (const float*)d_in[18];
    const float* be2     = (const float*)d_in[19];
    const float* Wn1     = (const float*)d_in[20];
    const float* bn1     = (const float*)d_in[21];
    const float* Wn2     = (const float*)d_in[22];
    const float* bn2     = (const float*)d_in[23];
    const float* g3      = (const float*)d_in[24];
    const float* be3     = (const float*)d_in[25];
    const float* Wu1     = (const float*)d_in[26];
    const float* bu1     = (const float*)d_in[27];
    const float* Wu2     = (const float*)d_in[28];
    const float* bu2     = (const float*)d_in[29];
    float* out = (float*)d_out;

    cudaFuncSetAttribute(k_attn, cudaFuncAttributeMaxDynamicSharedMemorySize,
                         SMEM_ATTN_BYTES);

    k_ln1 <<<BT_ / 8, 256>>>(x, g1, be1);
    k_topk<<<T_ / 4, 128>>>(coords1, coords2);
    k_bias<<<T_, 256>>>(Wp1, bp1, Wp2, bp2);
    k_attn<<<1184, 256, SMEM_ATTN_BYTES>>>(Wq, bq, Wk, bk, Wv, bv, ls, Wo, bo,
                                           g2, be2, Wn1, bn1, Wn2, bn2, g3, be3);
    k_head<<<BT_ / 64, 256>>>(Wu1, bu1, Wu2, bu2, out);
}